// round 1
// baseline (speedup 1.0000x reference)
#include <cuda_runtime.h>
#include <math.h>
#include <stdint.h>

// Problem capacities (fixed shapes per reference)
#define NMAXN 50000
#define EMAXE 200000
#define ETOTMAX (EMAXE + NMAXN)
#define GMAXG 1000

// ---------------- scratch (static device memory; no allocations allowed) ----
__device__ float g_bufA[(size_t)NMAXN * 1024];
__device__ float g_bufB[(size_t)NMAXN * 1024];
__device__ float g_bufC[(size_t)NMAXN * 1024];
__device__ float g_alS[NMAXN * 4];
__device__ float g_alD[NMAXN * 4];
__device__ float g_m[NMAXN * 4];
__device__ float g_ssum[NMAXN * 4];
__device__ float g_ex[(size_t)ETOTMAX * 4];
__device__ float g_deg[NMAXN];
__device__ float g_bnsum[1024];
__device__ float g_bnsq[1024];
__device__ float g_bnscale[1024];
__device__ float g_bnshift[1024];
__device__ float g_cnt[GMAXG];
__device__ float g_z[GMAXG * 640];
__device__ float g_zf[GMAXG * 128];

// ---------------- helpers ---------------------------------------------------
__device__ __forceinline__ void atomicMaxFloat(float* addr, float val) {
    if (val >= 0.0f) {
        atomicMax((int*)addr, __float_as_int(val));
    } else {
        atomicMin((unsigned int*)addr, __float_as_uint(val));
    }
}

__device__ __forceinline__ void edge_sd(const int* __restrict__ ei, int E, int e,
                                        int& s, int& d) {
    if (e < E) { s = ei[e]; d = ei[E + e]; }
    else       { s = e - E; d = e - E; }
}

__global__ void fill_kernel(float* p, size_t nelem, float v) {
    for (size_t i = (size_t)blockIdx.x * blockDim.x + threadIdx.x; i < nelem;
         i += (size_t)gridDim.x * blockDim.x)
        p[i] = v;
}

// ---------------- SGEMM: C[M,Nc] = A[M,K] @ B[K,Nc] (+bias, opt relu) --------
// BM=BN=128, BK=8, 256 threads, 8x8 per thread. Requires Nc % 128 == 0, K % 8 == 0.
template <bool RELU>
__global__ __launch_bounds__(256) void sgemm(
    const float* __restrict__ A, const float* __restrict__ B,
    const float* __restrict__ bias, float* __restrict__ C,
    int M, int Nc, int K, int lda, int ldc)
{
    __shared__ float As[8][128];
    __shared__ float Bs[8][128];

    int tid = threadIdx.x;
    int bx = blockIdx.x;  // column block
    int by = blockIdx.y;  // row block

    int tx = tid % 16;    // col group
    int ty = tid / 16;    // row group

    int rowA = by * 128 + tid / 2;
    int colA = (tid % 2) * 4;
    int rowB = tid / 32;
    int colB = (tid % 32) * 4;

    float acc[8][8];
#pragma unroll
    for (int i = 0; i < 8; i++)
#pragma unroll
        for (int j = 0; j < 8; j++) acc[i][j] = 0.0f;

    for (int k0 = 0; k0 < K; k0 += 8) {
        float4 av = make_float4(0.f, 0.f, 0.f, 0.f);
        if (rowA < M)
            av = *(const float4*)(A + (size_t)rowA * lda + k0 + colA);
        As[colA + 0][tid / 2] = av.x;
        As[colA + 1][tid / 2] = av.y;
        As[colA + 2][tid / 2] = av.z;
        As[colA + 3][tid / 2] = av.w;

        float4 bv = *(const float4*)(B + (size_t)(k0 + rowB) * Nc + bx * 128 + colB);
        *(float4*)(&Bs[rowB][colB]) = bv;

        __syncthreads();

#pragma unroll
        for (int kk = 0; kk < 8; kk++) {
            float ra[8], rb[8];
#pragma unroll
            for (int i = 0; i < 8; i++) ra[i] = As[kk][ty * 8 + i];
#pragma unroll
            for (int j = 0; j < 8; j++) rb[j] = Bs[kk][tx * 8 + j];
#pragma unroll
            for (int i = 0; i < 8; i++)
#pragma unroll
                for (int j = 0; j < 8; j++) acc[i][j] = fmaf(ra[i], rb[j], acc[i][j]);
        }
        __syncthreads();
    }

#pragma unroll
    for (int i = 0; i < 8; i++) {
        int row = by * 128 + ty * 8 + i;
        if (row >= M) continue;
#pragma unroll
        for (int j = 0; j < 8; j++) {
            int col = bx * 128 + tx * 8 + j;
            float v = acc[i][j];
            if (bias) v += bias[col];
            if (RELU) v = v > 0.f ? v : 0.f;
            C[(size_t)row * ldc + col] = v;
        }
    }
}

// ---------------- GAT attention ---------------------------------------------
// al_s[n,h] = sum_c h[n,h,c]*a_src[h,c]; one warp per (node,head)
__global__ void gat_alphas(const float* __restrict__ h, const float* __restrict__ aS,
                           const float* __restrict__ aD, float* __restrict__ alS,
                           float* __restrict__ alD, int n, int C)
{
    int warp = (blockIdx.x * blockDim.x + threadIdx.x) >> 5;
    int lane = threadIdx.x & 31;
    if (warp >= n * 4) return;
    int node = warp >> 2;
    int hh = warp & 3;
    const float* hp = h + (size_t)node * 4 * C + hh * C;
    const float* as = aS + hh * C;
    const float* ad = aD + hh * C;
    float s = 0.f, d = 0.f;
    for (int c = lane; c < C; c += 32) {
        float v = hp[c];
        s += v * as[c];
        d += v * ad[c];
    }
#pragma unroll
    for (int o = 16; o; o >>= 1) {
        s += __shfl_down_sync(0xFFFFFFFFu, s, o);
        d += __shfl_down_sync(0xFFFFFFFFu, d, o);
    }
    if (lane == 0) { alS[node * 4 + hh] = s; alD[node * 4 + hh] = d; }
}

__global__ void edge_logits(const int* __restrict__ ei, int E, int Etot,
                            const float* __restrict__ alS, const float* __restrict__ alD,
                            float* __restrict__ ex, float* __restrict__ m)
{
    int e = blockIdx.x * blockDim.x + threadIdx.x;
    if (e >= Etot) return;
    int s, d; edge_sd(ei, E, e, s, d);
    float4 a = *(const float4*)(alS + (size_t)s * 4);
    float4 b = *(const float4*)(alD + (size_t)d * 4);
    float v[4] = {a.x + b.x, a.y + b.y, a.z + b.z, a.w + b.w};
#pragma unroll
    for (int h = 0; h < 4; h++) {
        float t = v[h];
        t = t > 0.f ? t : 0.2f * t;   // leaky relu
        v[h] = t;
        atomicMaxFloat(m + (size_t)d * 4 + h, t);
    }
    *(float4*)(ex + (size_t)e * 4) = make_float4(v[0], v[1], v[2], v[3]);
}

__global__ void edge_exp(const int* __restrict__ ei, int E, int Etot,
                         const float* __restrict__ m, float* __restrict__ ex,
                         float* __restrict__ ssum)
{
    int e = blockIdx.x * blockDim.x + threadIdx.x;
    if (e >= Etot) return;
    int s, d; edge_sd(ei, E, e, s, d);
    float4 v = *(float4*)(ex + (size_t)e * 4);
    float4 mv = *(const float4*)(m + (size_t)d * 4);
    v.x = expf(v.x - mv.x);
    v.y = expf(v.y - mv.y);
    v.z = expf(v.z - mv.z);
    v.w = expf(v.w - mv.w);
    *(float4*)(ex + (size_t)e * 4) = v;
    atomicAdd(ssum + (size_t)d * 4 + 0, v.x);
    atomicAdd(ssum + (size_t)d * 4 + 1, v.y);
    atomicAdd(ssum + (size_t)d * 4 + 2, v.z);
    atomicAdd(ssum + (size_t)d * 4 + 3, v.w);
}

// one block per edge, HC/4 threads, each does a float4 slice
__global__ void gat_agg(const int* __restrict__ ei, int E,
                        const float* __restrict__ h, const float* __restrict__ ex,
                        const float* __restrict__ ssum, float* __restrict__ out,
                        int C, int HC)
{
    int e = blockIdx.x;
    int s, d; edge_sd(ei, E, e, s, d);
    int f = threadIdx.x * 4;
    int hh = f / C;
    float alpha = ex[(size_t)e * 4 + hh] / fmaxf(ssum[(size_t)d * 4 + hh], 1e-16f);
    float4 hv = *(const float4*)(h + (size_t)s * HC + f);
    float* o = out + (size_t)d * HC + f;
    atomicAdd(o + 0, hv.x * alpha);
    atomicAdd(o + 1, hv.y * alpha);
    atomicAdd(o + 2, hv.z * alpha);
    atomicAdd(o + 3, hv.w * alpha);
}

// ---------------- GCN -------------------------------------------------------
__global__ void deg_kernel(const int* __restrict__ ei, int E, int Etot,
                           float* __restrict__ deg)
{
    int e = blockIdx.x * blockDim.x + threadIdx.x;
    if (e >= Etot) return;
    int s, d; edge_sd(ei, E, e, s, d);
    (void)s;
    atomicAdd(deg + d, 1.0f);
}

__global__ void gcn_agg(const int* __restrict__ ei, int E,
                        const float* __restrict__ h, const float* __restrict__ deg,
                        float* __restrict__ out)
{
    int e = blockIdx.x;
    int s, d; edge_sd(ei, E, e, s, d);
    float norm = rsqrtf(fmaxf(deg[s], 1.f)) * rsqrtf(fmaxf(deg[d], 1.f));
    int f = threadIdx.x * 4;
    float4 hv = *(const float4*)(h + (size_t)s * 256 + f);
    float* o = out + (size_t)d * 256 + f;
    atomicAdd(o + 0, hv.x * norm);
    atomicAdd(o + 1, hv.y * norm);
    atomicAdd(o + 2, hv.z * norm);
    atomicAdd(o + 3, hv.w * norm);
}

// ---------------- BatchNorm -------------------------------------------------
__global__ void bn_stats(const float* __restrict__ x, int rows, int K,
                         float* __restrict__ sum, float* __restrict__ sq)
{
    int col = blockIdx.x * blockDim.x + threadIdx.x;  // gridDim.x*blockDim.x == K
    float s = 0.f, q = 0.f;
    for (int r = blockIdx.y; r < rows; r += gridDim.y) {
        float v = x[(size_t)r * K + col];
        s += v;
        q += v * v;
    }
    atomicAdd(sum + col, s);
    atomicAdd(sq + col, q);
}

__global__ void bn_finalize(const float* __restrict__ sum, const float* __restrict__ sq,
                            const float* __restrict__ g, const float* __restrict__ b,
                            int rows, int K, float* __restrict__ scale,
                            float* __restrict__ shift)
{
    int c = blockIdx.x * blockDim.x + threadIdx.x;
    if (c >= K) return;
    float inv_n = 1.0f / (float)rows;
    float mu = sum[c] * inv_n;
    float var = sq[c] * inv_n - mu * mu;
    float sc = g[c] * rsqrtf(var + 1e-5f);
    scale[c] = sc;
    shift[c] = b[c] - mu * sc;
}

__global__ void bn_apply_relu(float* __restrict__ x, const float* __restrict__ scale,
                              const float* __restrict__ shift, size_t total, int K)
{
    for (size_t i = (size_t)blockIdx.x * blockDim.x + threadIdx.x; i < total;
         i += (size_t)gridDim.x * blockDim.x) {
        int c = (int)(i % K);
        float v = x[i] * scale[c] + shift[c];
        x[i] = v > 0.f ? v : 0.f;
    }
}

// ---------------- Pooling ---------------------------------------------------
__global__ void pool_cnt(const int* __restrict__ batch, int n, float* __restrict__ cnt)
{
    int i = blockIdx.x * blockDim.x + threadIdx.x;
    if (i >= n) return;
    atomicAdd(cnt + batch[i], 1.0f);
}

__global__ void pool_kernel(const float* __restrict__ h, const int* __restrict__ batch,
                            int n, float* __restrict__ z)
{
    size_t total = (size_t)n * 256;
    for (size_t i = (size_t)blockIdx.x * blockDim.x + threadIdx.x; i < total;
         i += (size_t)gridDim.x * blockDim.x) {
        int node = (int)(i >> 8);
        int c = (int)(i & 255);
        int g = batch[node];
        float v = h[i];
        atomicAdd(z + (size_t)g * 640 + c, v);
        // values are post-relu >= 0, so int-compare atomicMax is valid with 0 init
        atomicMax((int*)(z + (size_t)g * 640 + 256 + c), __float_as_int(v));
    }
}

__global__ void pool_div(float* __restrict__ z, const float* __restrict__ cnt, int G)
{
    int i = blockIdx.x * blockDim.x + threadIdx.x;
    if (i >= G * 256) return;
    int g = i >> 8;
    int c = i & 255;
    z[(size_t)g * 640 + c] /= fmaxf(cnt[g], 1.0f);
}

// ---------------- Head ------------------------------------------------------
__global__ void head_final(const float* __restrict__ zf, const float* __restrict__ Wf2,
                           const float* __restrict__ bf2, float* __restrict__ out)
{
    int g = blockIdx.x;
    int t = threadIdx.x;  // 128 threads
    float v = zf[(size_t)g * 128 + t] * Wf2[t];
#pragma unroll
    for (int o = 16; o; o >>= 1) v += __shfl_down_sync(0xFFFFFFFFu, v, o);
    __shared__ float sm[4];
    if ((t & 31) == 0) sm[t >> 5] = v;
    __syncthreads();
    if (t == 0) {
        float s = sm[0] + sm[1] + sm[2] + sm[3] + bf2[0];
        out[g] = 1.0f / (1.0f + expf(-s));
    }
}

// ---------------- launch ----------------------------------------------------
extern "C" void kernel_launch(void* const* d_in, const int* in_sizes, int n_in,
                              void* d_out, int out_size)
{
    const float* x    = (const float*)d_in[0];
    const int*   ei   = (const int*)d_in[1];
    const int*   batch= (const int*)d_in[2];
    const float* fp   = (const float*)d_in[3];
    const float* W1   = (const float*)d_in[4];
    const float* a1s  = (const float*)d_in[5];
    const float* a1d  = (const float*)d_in[6];
    // d_in[7]  = b1   (cancels under BN)
    const float* bn1g = (const float*)d_in[8];
    const float* bn1b = (const float*)d_in[9];
    const float* W2   = (const float*)d_in[10];
    const float* a2s  = (const float*)d_in[11];
    const float* a2d  = (const float*)d_in[12];
    // d_in[13] = b2   (cancels under BN)
    const float* bn2g = (const float*)d_in[14];
    const float* bn2b = (const float*)d_in[15];
    const float* Wg   = (const float*)d_in[16];
    // d_in[17] = bg   (cancels under BN)
    const float* bn3g = (const float*)d_in[18];
    const float* bn3b = (const float*)d_in[19];
    const float* Ws   = (const float*)d_in[20];
    const float* bs   = (const float*)d_in[21];
    const float* Wf1  = (const float*)d_in[22];
    // d_in[23] = bf1  (cancels under BN)
    const float* bnfg = (const float*)d_in[24];
    const float* bnfb = (const float*)d_in[25];
    const float* Wf2  = (const float*)d_in[26];
    const float* bf2  = (const float*)d_in[27];
    float* out = (float*)d_out;

    int n    = in_sizes[0] / 64;
    int E    = in_sizes[1] / 2;
    int Etot = E + n;
    int G    = in_sizes[3] / 128;

    float *bufA, *bufB, *bufC, *alS, *alD, *m, *ssum, *ex, *deg;
    float *bnsum, *bnsq, *bnscale, *bnshift, *cnt, *z, *zf;
    cudaGetSymbolAddress((void**)&bufA, g_bufA);
    cudaGetSymbolAddress((void**)&bufB, g_bufB);
    cudaGetSymbolAddress((void**)&bufC, g_bufC);
    cudaGetSymbolAddress((void**)&alS, g_alS);
    cudaGetSymbolAddress((void**)&alD, g_alD);
    cudaGetSymbolAddress((void**)&m, g_m);
    cudaGetSymbolAddress((void**)&ssum, g_ssum);
    cudaGetSymbolAddress((void**)&ex, g_ex);
    cudaGetSymbolAddress((void**)&deg, g_deg);
    cudaGetSymbolAddress((void**)&bnsum, g_bnsum);
    cudaGetSymbolAddress((void**)&bnsq, g_bnsq);
    cudaGetSymbolAddress((void**)&bnscale, g_bnscale);
    cudaGetSymbolAddress((void**)&bnshift, g_bnshift);
    cudaGetSymbolAddress((void**)&cnt, g_cnt);
    cudaGetSymbolAddress((void**)&z, g_z);
    cudaGetSymbolAddress((void**)&zf, g_zf);

    auto gemm = [&](const float* A, const float* B, const float* bias, float* C,
                    int M, int Nc, int K, int lda, int ldc, bool relu) {
        dim3 grid(Nc / 128, (M + 127) / 128);
        if (relu) sgemm<true><<<grid, 256>>>(A, B, bias, C, M, Nc, K, lda, ldc);
        else      sgemm<false><<<grid, 256>>>(A, B, bias, C, M, Nc, K, lda, ldc);
    };

    auto batchnorm = [&](float* Xp, int rows, int K, const float* gg, const float* bb) {
        cudaMemsetAsync(bnsum, 0, K * sizeof(float));
        cudaMemsetAsync(bnsq, 0, K * sizeof(float));
        dim3 g1(K / 128, 128);
        bn_stats<<<g1, 128>>>(Xp, rows, K, bnsum, bnsq);
        bn_finalize<<<(K + 127) / 128, 128>>>(bnsum, bnsq, gg, bb, rows, K, bnscale, bnshift);
        size_t tot = (size_t)rows * K;
        int blocks = (int)((tot + 255) / 256);
        if (blocks > 65535 * 8) blocks = 65535 * 8;
        bn_apply_relu<<<blocks, 256>>>(Xp, bnscale, bnshift, tot, K);
    };

    auto gat_attention = [&](const float* h, const float* as, const float* ad,
                             int C, int HC, float* outp) {
        gat_alphas<<<(n * 4 + 7) / 8, 256>>>(h, as, ad, alS, alD, n, C);
        fill_kernel<<<512, 256>>>(m, (size_t)n * 4, -INFINITY);
        cudaMemsetAsync(ssum, 0, (size_t)n * 4 * sizeof(float));
        cudaMemsetAsync(outp, 0, (size_t)n * HC * sizeof(float));
        edge_logits<<<(Etot + 255) / 256, 256>>>(ei, E, Etot, alS, alD, ex, m);
        edge_exp<<<(Etot + 255) / 256, 256>>>(ei, E, Etot, m, ex, ssum);
        gat_agg<<<Etot, HC / 4>>>(ei, E, h, ex, ssum, outp, C, HC);
    };

    // ---- GAT layer 1: x[N,64] -> bufA[N,512] -> attention -> bufB[N,512]
    gemm(x, W1, nullptr, bufA, n, 512, 64, 64, 512, false);
    gat_attention(bufA, a1s, a1d, 128, 512, bufB);
    batchnorm(bufB, n, 512, bn1g, bn1b);

    // ---- GAT layer 2: bufB[N,512] -> bufC[N,1024] -> attention -> bufA[N,1024]
    gemm(bufB, W2, nullptr, bufC, n, 1024, 512, 512, 1024, false);
    gat_attention(bufC, a2s, a2d, 256, 1024, bufA);
    batchnorm(bufA, n, 1024, bn2g, bn2b);

    // ---- GCN: bufA[N,1024] @ Wg -> bufB[N,256]; aggregate -> bufC[N,256]
    gemm(bufA, Wg, nullptr, bufB, n, 256, 1024, 1024, 256, false);
    cudaMemsetAsync(deg, 0, (size_t)n * sizeof(float));
    deg_kernel<<<(Etot + 255) / 256, 256>>>(ei, E, Etot, deg);
    cudaMemsetAsync(bufC, 0, (size_t)n * 256 * sizeof(float));
    gcn_agg<<<Etot, 64>>>(ei, E, bufB, deg, bufC);
    batchnorm(bufC, n, 256, bn3g, bn3b);

    // ---- Pooling into z[G,640]: gap [0:256), gmp [256:512), solv [512:640)
    cudaMemsetAsync(cnt, 0, G * sizeof(float));
    cudaMemsetAsync(z, 0, (size_t)G * 640 * sizeof(float));
    pool_cnt<<<(n + 255) / 256, 256>>>(batch, n, cnt);
    pool_kernel<<<8192, 256>>>(bufC, batch, n, z);
    pool_div<<<(G * 256 + 255) / 256, 256>>>(z, cnt, G);

    // ---- solvent MLP: relu(fp @ Ws + bs) -> z[:,512:640]
    gemm(fp, Ws, bs, z + 512, G, 128, 128, 128, 640, true);

    // ---- head: zf = z @ Wf1 (bf1 cancels under BN); BN; relu; sigmoid(zf @ Wf2 + bf2)
    gemm(z, Wf1, nullptr, zf, G, 128, 640, 640, 128, false);
    {
        cudaMemsetAsync(bnsum, 0, 128 * sizeof(float));
        cudaMemsetAsync(bnsq, 0, 128 * sizeof(float));
        dim3 g1(1, 128);
        bn_stats<<<g1, 128>>>(zf, G, 128, bnsum, bnsq);
        bn_finalize<<<1, 128>>>(bnsum, bnsq, bnfg, bnfb, G, 128, bnscale, bnshift);
        bn_apply_relu<<<((size_t)G * 128 + 255) / 256, 256>>>(zf, bnscale, bnshift,
                                                              (size_t)G * 128, 128);
    }
    head_final<<<G, 128>>>(zf, Wf2, bf2, out);
}

// round 2
// speedup vs baseline: 1.5103x; 1.5103x over previous
#include <cuda_runtime.h>
#include <math.h>
#include <stdint.h>

// Problem capacities (fixed shapes per reference)
#define NMAXN 50000
#define EMAXE 200000
#define ETOTMAX (EMAXE + NMAXN)
#define GMAXG 1000

// ---------------- scratch (static device memory; no allocations allowed) ----
__device__ float g_bufA[(size_t)NMAXN * 1024];
__device__ float g_bufB[(size_t)NMAXN * 1024];
__device__ float g_bufC[(size_t)NMAXN * 1024];
__device__ float g_alS[NMAXN * 4];
__device__ float g_alD[NMAXN * 4];
__device__ float g_m[NMAXN * 4];
__device__ float g_ssum[NMAXN * 4];
__device__ float g_ex[(size_t)ETOTMAX * 4];
__device__ float g_deg[NMAXN];
__device__ float g_bnsum[1024];
__device__ float g_bnsq[1024];
__device__ float g_bnscale[1024];
__device__ float g_bnshift[1024];
__device__ float g_cnt[GMAXG];
__device__ float g_z[GMAXG * 640];
__device__ float g_zf[GMAXG * 128];

// ---------------- helpers ---------------------------------------------------
__device__ __forceinline__ void atomicMaxFloat(float* addr, float val) {
    if (val >= 0.0f) {
        atomicMax((int*)addr, __float_as_int(val));
    } else {
        atomicMin((unsigned int*)addr, __float_as_uint(val));
    }
}

__device__ __forceinline__ void edge_sd(const int* __restrict__ ei, int E, int e,
                                        int& s, int& d) {
    if (e < E) { s = ei[e]; d = ei[E + e]; }
    else       { s = e - E; d = e - E; }
}

__global__ void fill_kernel(float* p, size_t nelem, float v) {
    for (size_t i = (size_t)blockIdx.x * blockDim.x + threadIdx.x; i < nelem;
         i += (size_t)gridDim.x * blockDim.x)
        p[i] = v;
}

// ---------------- TF32 tensor-core GEMM -------------------------------------
// C[M,Nc] = A[M,K] @ B[K,Nc], row-major all. Nc%128==0, K%32==0, lda=K, ldc=Nc.
// Block 128x128x32, 256 threads, 8 warps as 2(M) x 4(N), warp tile 64x32.
__device__ __forceinline__ float to_tf32(float x) {
    uint32_t u;
    asm("cvt.rna.tf32.f32 %0, %1;" : "=r"(u) : "f"(x));
    return __uint_as_float(u);
}

__device__ __forceinline__ void mma_tf32(float c[4], const float a[4], const float b[2]) {
    asm volatile(
        "mma.sync.aligned.m16n8k8.row.col.f32.tf32.tf32.f32 "
        "{%0,%1,%2,%3}, {%4,%5,%6,%7}, {%8,%9}, {%0,%1,%2,%3};"
        : "+f"(c[0]), "+f"(c[1]), "+f"(c[2]), "+f"(c[3])
        : "r"(__float_as_uint(a[0])), "r"(__float_as_uint(a[1])),
          "r"(__float_as_uint(a[2])), "r"(__float_as_uint(a[3])),
          "r"(__float_as_uint(b[0])), "r"(__float_as_uint(b[1])));
}

__global__ __launch_bounds__(256, 2) void tf32gemm(
    const float* __restrict__ A, const float* __restrict__ B,
    float* __restrict__ C, int M, int Nc, int K)
{
    __shared__ float As[128][36];   // [m][k], pitch 36: conflict-free frag LDS
    __shared__ float Bs[32][136];   // [k][n], pitch 136: conflict-free frag LDS

    int tid = threadIdx.x;
    int lane = tid & 31;
    int wid = tid >> 5;
    int warpM = (wid >> 2) * 64;   // 0 or 64
    int warpN = (wid & 3) * 32;    // 0,32,64,96
    int r = lane >> 2;             // 0..7
    int cq = lane & 3;             // 0..3

    int blockM = blockIdx.y * 128;
    int blockN = blockIdx.x * 128;

    // gmem->smem mappings
    int acol = (tid & 7) * 4;      // 0..28
    int arow0 = tid >> 3;          // 0..31
    int bcol = (tid & 31) * 4;     // 0..124
    int brow0 = tid >> 5;          // 0..7

    float acc[4][4][4];
#pragma unroll
    for (int mt = 0; mt < 4; mt++)
#pragma unroll
        for (int nt = 0; nt < 4; nt++)
#pragma unroll
            for (int i = 0; i < 4; i++) acc[mt][nt][i] = 0.0f;

    for (int k0 = 0; k0 < K; k0 += 32) {
#pragma unroll
        for (int i = 0; i < 4; i++) {
            int row = blockM + arow0 + i * 32;
            float4 v = make_float4(0.f, 0.f, 0.f, 0.f);
            if (row < M) v = *(const float4*)(A + (size_t)row * K + k0 + acol);
            v.x = to_tf32(v.x); v.y = to_tf32(v.y);
            v.z = to_tf32(v.z); v.w = to_tf32(v.w);
            *(float4*)&As[arow0 + i * 32][acol] = v;
        }
#pragma unroll
        for (int i = 0; i < 4; i++) {
            int kr = brow0 + i * 8;
            float4 v = *(const float4*)(B + (size_t)(k0 + kr) * Nc + blockN + bcol);
            v.x = to_tf32(v.x); v.y = to_tf32(v.y);
            v.z = to_tf32(v.z); v.w = to_tf32(v.w);
            *(float4*)&Bs[kr][bcol] = v;
        }
        __syncthreads();

#pragma unroll
        for (int kk = 0; kk < 4; kk++) {
            int kb = kk * 8;
            float a[4][4], b[4][2];
#pragma unroll
            for (int mt = 0; mt < 4; mt++) {
                int m = warpM + mt * 16 + r;
                a[mt][0] = As[m][kb + cq];
                a[mt][1] = As[m + 8][kb + cq];
                a[mt][2] = As[m][kb + cq + 4];
                a[mt][3] = As[m + 8][kb + cq + 4];
            }
#pragma unroll
            for (int nt = 0; nt < 4; nt++) {
                int n = warpN + nt * 8 + r;
                b[nt][0] = Bs[kb + cq][n];
                b[nt][1] = Bs[kb + cq + 4][n];
            }
#pragma unroll
            for (int mt = 0; mt < 4; mt++)
#pragma unroll
                for (int nt = 0; nt < 4; nt++)
                    mma_tf32(acc[mt][nt], a[mt], b[nt]);
        }
        __syncthreads();
    }

    // epilogue: c0=[r, 2cq], c1=[r, 2cq+1], c2=[r+8, 2cq], c3=[r+8, 2cq+1]
#pragma unroll
    for (int mt = 0; mt < 4; mt++) {
        int row0 = blockM + warpM + mt * 16 + r;
#pragma unroll
        for (int nt = 0; nt < 4; nt++) {
            int col = blockN + warpN + nt * 8 + cq * 2;
            if (row0 < M)
                *(float2*)(C + (size_t)row0 * Nc + col) =
                    make_float2(acc[mt][nt][0], acc[mt][nt][1]);
            if (row0 + 8 < M)
                *(float2*)(C + (size_t)(row0 + 8) * Nc + col) =
                    make_float2(acc[mt][nt][2], acc[mt][nt][3]);
        }
    }
}

// ---------------- fp32 SGEMM (small head GEMMs) ------------------------------
template <bool RELU>
__global__ __launch_bounds__(256) void sgemm(
    const float* __restrict__ A, const float* __restrict__ B,
    const float* __restrict__ bias, float* __restrict__ C,
    int M, int Nc, int K, int lda, int ldc)
{
    __shared__ float As[8][128];
    __shared__ float Bs[8][128];

    int tid = threadIdx.x;
    int bx = blockIdx.x;
    int by = blockIdx.y;

    int tx = tid % 16;
    int ty = tid / 16;

    int rowA = by * 128 + tid / 2;
    int colA = (tid % 2) * 4;
    int rowB = tid / 32;
    int colB = (tid % 32) * 4;

    float acc[8][8];
#pragma unroll
    for (int i = 0; i < 8; i++)
#pragma unroll
        for (int j = 0; j < 8; j++) acc[i][j] = 0.0f;

    for (int k0 = 0; k0 < K; k0 += 8) {
        float4 av = make_float4(0.f, 0.f, 0.f, 0.f);
        if (rowA < M)
            av = *(const float4*)(A + (size_t)rowA * lda + k0 + colA);
        As[colA + 0][tid / 2] = av.x;
        As[colA + 1][tid / 2] = av.y;
        As[colA + 2][tid / 2] = av.z;
        As[colA + 3][tid / 2] = av.w;

        float4 bv = *(const float4*)(B + (size_t)(k0 + rowB) * Nc + bx * 128 + colB);
        *(float4*)(&Bs[rowB][colB]) = bv;

        __syncthreads();

#pragma unroll
        for (int kk = 0; kk < 8; kk++) {
            float ra[8], rb[8];
#pragma unroll
            for (int i = 0; i < 8; i++) ra[i] = As[kk][ty * 8 + i];
#pragma unroll
            for (int j = 0; j < 8; j++) rb[j] = Bs[kk][tx * 8 + j];
#pragma unroll
            for (int i = 0; i < 8; i++)
#pragma unroll
                for (int j = 0; j < 8; j++) acc[i][j] = fmaf(ra[i], rb[j], acc[i][j]);
        }
        __syncthreads();
    }

#pragma unroll
    for (int i = 0; i < 8; i++) {
        int row = by * 128 + ty * 8 + i;
        if (row >= M) continue;
#pragma unroll
        for (int j = 0; j < 8; j++) {
            int col = bx * 128 + tx * 8 + j;
            float v = acc[i][j];
            if (bias) v += bias[col];
            if (RELU) v = v > 0.f ? v : 0.f;
            C[(size_t)row * ldc + col] = v;
        }
    }
}

// ---------------- GAT attention ---------------------------------------------
__global__ void gat_alphas(const float* __restrict__ h, const float* __restrict__ aS,
                           const float* __restrict__ aD, float* __restrict__ alS,
                           float* __restrict__ alD, int n, int C)
{
    int warp = (blockIdx.x * blockDim.x + threadIdx.x) >> 5;
    int lane = threadIdx.x & 31;
    if (warp >= n * 4) return;
    int node = warp >> 2;
    int hh = warp & 3;
    const float* hp = h + (size_t)node * 4 * C + hh * C;
    const float* as = aS + hh * C;
    const float* ad = aD + hh * C;
    float s = 0.f, d = 0.f;
    for (int c = lane; c < C; c += 32) {
        float v = hp[c];
        s += v * as[c];
        d += v * ad[c];
    }
#pragma unroll
    for (int o = 16; o; o >>= 1) {
        s += __shfl_down_sync(0xFFFFFFFFu, s, o);
        d += __shfl_down_sync(0xFFFFFFFFu, d, o);
    }
    if (lane == 0) { alS[node * 4 + hh] = s; alD[node * 4 + hh] = d; }
}

__global__ void edge_logits(const int* __restrict__ ei, int E, int Etot,
                            const float* __restrict__ alS, const float* __restrict__ alD,
                            float* __restrict__ ex, float* __restrict__ m)
{
    int e = blockIdx.x * blockDim.x + threadIdx.x;
    if (e >= Etot) return;
    int s, d; edge_sd(ei, E, e, s, d);
    float4 a = *(const float4*)(alS + (size_t)s * 4);
    float4 b = *(const float4*)(alD + (size_t)d * 4);
    float v[4] = {a.x + b.x, a.y + b.y, a.z + b.z, a.w + b.w};
#pragma unroll
    for (int h = 0; h < 4; h++) {
        float t = v[h];
        t = t > 0.f ? t : 0.2f * t;   // leaky relu
        v[h] = t;
        atomicMaxFloat(m + (size_t)d * 4 + h, t);
    }
    *(float4*)(ex + (size_t)e * 4) = make_float4(v[0], v[1], v[2], v[3]);
}

__global__ void edge_exp(const int* __restrict__ ei, int E, int Etot,
                         const float* __restrict__ m, float* __restrict__ ex,
                         float* __restrict__ ssum)
{
    int e = blockIdx.x * blockDim.x + threadIdx.x;
    if (e >= Etot) return;
    int s, d; edge_sd(ei, E, e, s, d);
    float4 v = *(float4*)(ex + (size_t)e * 4);
    float4 mv = *(const float4*)(m + (size_t)d * 4);
    v.x = expf(v.x - mv.x);
    v.y = expf(v.y - mv.y);
    v.z = expf(v.z - mv.z);
    v.w = expf(v.w - mv.w);
    *(float4*)(ex + (size_t)e * 4) = v;
    atomicAdd(ssum + (size_t)d * 4 + 0, v.x);
    atomicAdd(ssum + (size_t)d * 4 + 1, v.y);
    atomicAdd(ssum + (size_t)d * 4 + 2, v.z);
    atomicAdd(ssum + (size_t)d * 4 + 3, v.w);
}

// one block per edge, HC/4 threads, each does a float4 slice
__global__ void gat_agg(const int* __restrict__ ei, int E,
                        const float* __restrict__ h, const float* __restrict__ ex,
                        const float* __restrict__ ssum, float* __restrict__ out,
                        int C, int HC)
{
    int e = blockIdx.x;
    int s, d; edge_sd(ei, E, e, s, d);
    int f = threadIdx.x * 4;
    int hh = f / C;
    float alpha = ex[(size_t)e * 4 + hh] / fmaxf(ssum[(size_t)d * 4 + hh], 1e-16f);
    float4 hv = *(const float4*)(h + (size_t)s * HC + f);
    float* o = out + (size_t)d * HC + f;
    atomicAdd(o + 0, hv.x * alpha);
    atomicAdd(o + 1, hv.y * alpha);
    atomicAdd(o + 2, hv.z * alpha);
    atomicAdd(o + 3, hv.w * alpha);
}

// ---------------- GCN -------------------------------------------------------
__global__ void deg_kernel(const int* __restrict__ ei, int E, int Etot,
                           float* __restrict__ deg)
{
    int e = blockIdx.x * blockDim.x + threadIdx.x;
    if (e >= Etot) return;
    int s, d; edge_sd(ei, E, e, s, d);
    (void)s;
    atomicAdd(deg + d, 1.0f);
}

__global__ void gcn_agg(const int* __restrict__ ei, int E,
                        const float* __restrict__ h, const float* __restrict__ deg,
                        float* __restrict__ out)
{
    int e = blockIdx.x;
    int s, d; edge_sd(ei, E, e, s, d);
    float norm = rsqrtf(fmaxf(deg[s], 1.f)) * rsqrtf(fmaxf(deg[d], 1.f));
    int f = threadIdx.x * 4;
    float4 hv = *(const float4*)(h + (size_t)s * 256 + f);
    float* o = out + (size_t)d * 256 + f;
    atomicAdd(o + 0, hv.x * norm);
    atomicAdd(o + 1, hv.y * norm);
    atomicAdd(o + 2, hv.z * norm);
    atomicAdd(o + 3, hv.w * norm);
}

// ---------------- BatchNorm -------------------------------------------------
__global__ void bn_stats(const float* __restrict__ x, int rows, int K,
                         float* __restrict__ sum, float* __restrict__ sq)
{
    int col = blockIdx.x * blockDim.x + threadIdx.x;
    float s = 0.f, q = 0.f;
    for (int r = blockIdx.y; r < rows; r += gridDim.y) {
        float v = x[(size_t)r * K + col];
        s += v;
        q += v * v;
    }
    atomicAdd(sum + col, s);
    atomicAdd(sq + col, q);
}

__global__ void bn_finalize(const float* __restrict__ sum, const float* __restrict__ sq,
                            const float* __restrict__ g, const float* __restrict__ b,
                            int rows, int K, float* __restrict__ scale,
                            float* __restrict__ shift)
{
    int c = blockIdx.x * blockDim.x + threadIdx.x;
    if (c >= K) return;
    float inv_n = 1.0f / (float)rows;
    float mu = sum[c] * inv_n;
    float var = sq[c] * inv_n - mu * mu;
    float sc = g[c] * rsqrtf(var + 1e-5f);
    scale[c] = sc;
    shift[c] = b[c] - mu * sc;
}

__global__ void bn_apply_relu(float* __restrict__ x, const float* __restrict__ scale,
                              const float* __restrict__ shift, size_t total, int K)
{
    for (size_t i = (size_t)blockIdx.x * blockDim.x + threadIdx.x; i < total;
         i += (size_t)gridDim.x * blockDim.x) {
        int c = (int)(i % K);
        float v = x[i] * scale[c] + shift[c];
        x[i] = v > 0.f ? v : 0.f;
    }
}

// ---------------- Pooling ---------------------------------------------------
__global__ void pool_cnt(const int* __restrict__ batch, int n, float* __restrict__ cnt)
{
    int i = blockIdx.x * blockDim.x + threadIdx.x;
    if (i >= n) return;
    atomicAdd(cnt + batch[i], 1.0f);
}

__global__ void pool_kernel(const float* __restrict__ h, const int* __restrict__ batch,
                            int n, float* __restrict__ z)
{
    size_t total = (size_t)n * 256;
    for (size_t i = (size_t)blockIdx.x * blockDim.x + threadIdx.x; i < total;
         i += (size_t)gridDim.x * blockDim.x) {
        int node = (int)(i >> 8);
        int c = (int)(i & 255);
        int g = batch[node];
        float v = h[i];
        atomicAdd(z + (size_t)g * 640 + c, v);
        atomicMax((int*)(z + (size_t)g * 640 + 256 + c), __float_as_int(v));
    }
}

__global__ void pool_div(float* __restrict__ z, const float* __restrict__ cnt, int G)
{
    int i = blockIdx.x * blockDim.x + threadIdx.x;
    if (i >= G * 256) return;
    int g = i >> 8;
    int c = i & 255;
    z[(size_t)g * 640 + c] /= fmaxf(cnt[g], 1.0f);
}

// ---------------- Head ------------------------------------------------------
__global__ void head_final(const float* __restrict__ zf, const float* __restrict__ Wf2,
                           const float* __restrict__ bf2, float* __restrict__ out)
{
    int g = blockIdx.x;
    int t = threadIdx.x;
    float v = zf[(size_t)g * 128 + t] * Wf2[t];
#pragma unroll
    for (int o = 16; o; o >>= 1) v += __shfl_down_sync(0xFFFFFFFFu, v, o);
    __shared__ float sm[4];
    if ((t & 31) == 0) sm[t >> 5] = v;
    __syncthreads();
    if (t == 0) {
        float s = sm[0] + sm[1] + sm[2] + sm[3] + bf2[0];
        out[g] = 1.0f / (1.0f + expf(-s));
    }
}

// ---------------- launch ----------------------------------------------------
extern "C" void kernel_launch(void* const* d_in, const int* in_sizes, int n_in,
                              void* d_out, int out_size)
{
    const float* x    = (const float*)d_in[0];
    const int*   ei   = (const int*)d_in[1];
    const int*   batch= (const int*)d_in[2];
    const float* fp   = (const float*)d_in[3];
    const float* W1   = (const float*)d_in[4];
    const float* a1s  = (const float*)d_in[5];
    const float* a1d  = (const float*)d_in[6];
    const float* bn1g = (const float*)d_in[8];
    const float* bn1b = (const float*)d_in[9];
    const float* W2   = (const float*)d_in[10];
    const float* a2s  = (const float*)d_in[11];
    const float* a2d  = (const float*)d_in[12];
    const float* bn2g = (const float*)d_in[14];
    const float* bn2b = (const float*)d_in[15];
    const float* Wg   = (const float*)d_in[16];
    const float* bn3g = (const float*)d_in[18];
    const float* bn3b = (const float*)d_in[19];
    const float* Ws   = (const float*)d_in[20];
    const float* bs   = (const float*)d_in[21];
    const float* Wf1  = (const float*)d_in[22];
    const float* bnfg = (const float*)d_in[24];
    const float* bnfb = (const float*)d_in[25];
    const float* Wf2  = (const float*)d_in[26];
    const float* bf2  = (const float*)d_in[27];
    float* out = (float*)d_out;

    int n    = in_sizes[0] / 64;
    int E    = in_sizes[1] / 2;
    int Etot = E + n;
    int G    = in_sizes[3] / 128;

    float *bufA, *bufB, *bufC, *alS, *alD, *m, *ssum, *ex, *deg;
    float *bnsum, *bnsq, *bnscale, *bnshift, *cnt, *z, *zf;
    cudaGetSymbolAddress((void**)&bufA, g_bufA);
    cudaGetSymbolAddress((void**)&bufB, g_bufB);
    cudaGetSymbolAddress((void**)&bufC, g_bufC);
    cudaGetSymbolAddress((void**)&alS, g_alS);
    cudaGetSymbolAddress((void**)&alD, g_alD);
    cudaGetSymbolAddress((void**)&m, g_m);
    cudaGetSymbolAddress((void**)&ssum, g_ssum);
    cudaGetSymbolAddress((void**)&ex, g_ex);
    cudaGetSymbolAddress((void**)&deg, g_deg);
    cudaGetSymbolAddress((void**)&bnsum, g_bnsum);
    cudaGetSymbolAddress((void**)&bnsq, g_bnsq);
    cudaGetSymbolAddress((void**)&bnscale, g_bnscale);
    cudaGetSymbolAddress((void**)&bnshift, g_bnshift);
    cudaGetSymbolAddress((void**)&cnt, g_cnt);
    cudaGetSymbolAddress((void**)&z, g_z);
    cudaGetSymbolAddress((void**)&zf, g_zf);

    auto gemm_tc = [&](const float* A, const float* B, float* C,
                       int M, int Nc, int K) {
        dim3 grid(Nc / 128, (M + 127) / 128);
        tf32gemm<<<grid, 256>>>(A, B, C, M, Nc, K);
    };

    auto gemm = [&](const float* A, const float* B, const float* bias, float* C,
                    int M, int Nc, int K, int lda, int ldc, bool relu) {
        dim3 grid(Nc / 128, (M + 127) / 128);
        if (relu) sgemm<true><<<grid, 256>>>(A, B, bias, C, M, Nc, K, lda, ldc);
        else      sgemm<false><<<grid, 256>>>(A, B, bias, C, M, Nc, K, lda, ldc);
    };

    auto batchnorm = [&](float* Xp, int rows, int K, const float* gg, const float* bb) {
        cudaMemsetAsync(bnsum, 0, K * sizeof(float));
        cudaMemsetAsync(bnsq, 0, K * sizeof(float));
        dim3 g1(K / 128, 128);
        bn_stats<<<g1, 128>>>(Xp, rows, K, bnsum, bnsq);
        bn_finalize<<<(K + 127) / 128, 128>>>(bnsum, bnsq, gg, bb, rows, K, bnscale, bnshift);
        size_t tot = (size_t)rows * K;
        int blocks = (int)((tot + 255) / 256);
        if (blocks > 65535 * 8) blocks = 65535 * 8;
        bn_apply_relu<<<blocks, 256>>>(Xp, bnscale, bnshift, tot, K);
    };

    auto gat_attention = [&](const float* h, const float* as, const float* ad,
                             int C, int HC, float* outp) {
        gat_alphas<<<(n * 4 + 7) / 8, 256>>>(h, as, ad, alS, alD, n, C);
        fill_kernel<<<512, 256>>>(m, (size_t)n * 4, -INFINITY);
        cudaMemsetAsync(ssum, 0, (size_t)n * 4 * sizeof(float));
        cudaMemsetAsync(outp, 0, (size_t)n * HC * sizeof(float));
        edge_logits<<<(Etot + 255) / 256, 256>>>(ei, E, Etot, alS, alD, ex, m);
        edge_exp<<<(Etot + 255) / 256, 256>>>(ei, E, Etot, m, ex, ssum);
        gat_agg<<<Etot, HC / 4>>>(ei, E, h, ex, ssum, outp, C, HC);
    };

    // ---- GAT layer 1: x[N,64] -> bufA[N,512] -> attention -> bufB[N,512]
    gemm_tc(x, W1, bufA, n, 512, 64);
    gat_attention(bufA, a1s, a1d, 128, 512, bufB);
    batchnorm(bufB, n, 512, bn1g, bn1b);

    // ---- GAT layer 2: bufB[N,512] -> bufC[N,1024] -> attention -> bufA[N,1024]
    gemm_tc(bufB, W2, bufC, n, 1024, 512);
    gat_attention(bufC, a2s, a2d, 256, 1024, bufA);
    batchnorm(bufA, n, 1024, bn2g, bn2b);

    // ---- GCN: bufA[N,1024] @ Wg -> bufB[N,256]; aggregate -> bufC[N,256]
    gemm_tc(bufA, Wg, bufB, n, 256, 1024);
    cudaMemsetAsync(deg, 0, (size_t)n * sizeof(float));
    deg_kernel<<<(Etot + 255) / 256, 256>>>(ei, E, Etot, deg);
    cudaMemsetAsync(bufC, 0, (size_t)n * 256 * sizeof(float));
    gcn_agg<<<Etot, 64>>>(ei, E, bufB, deg, bufC);
    batchnorm(bufC, n, 256, bn3g, bn3b);

    // ---- Pooling into z[G,640]: gap [0:256), gmp [256:512), solv [512:640)
    cudaMemsetAsync(cnt, 0, G * sizeof(float));
    cudaMemsetAsync(z, 0, (size_t)G * 640 * sizeof(float));
    pool_cnt<<<(n + 255) / 256, 256>>>(batch, n, cnt);
    pool_kernel<<<8192, 256>>>(bufC, batch, n, z);
    pool_div<<<(G * 256 + 255) / 256, 256>>>(z, cnt, G);

    // ---- solvent MLP: relu(fp @ Ws + bs) -> z[:,512:640]
    gemm(fp, Ws, bs, z + 512, G, 128, 128, 128, 640, true);

    // ---- head: zf = z @ Wf1 (bf1 cancels under BN); BN; relu; sigmoid
    gemm(z, Wf1, nullptr, zf, G, 128, 640, 640, 128, false);
    {
        cudaMemsetAsync(bnsum, 0, 128 * sizeof(float));
        cudaMemsetAsync(bnsq, 0, 128 * sizeof(float));
        dim3 g1(1, 128);
        bn_stats<<<g1, 128>>>(zf, G, 128, bnsum, bnsq);
        bn_finalize<<<1, 128>>>(bnsum, bnsq, bnfg, bnfb, G, 128, bnscale, bnshift);
        bn_apply_relu<<<((size_t)G * 128 + 255) / 256, 256>>>(zf, bnscale, bnshift,
                                                              (size_t)G * 128, 128);
    }
    head_final<<<G, 128>>>(zf, Wf2, bf2, out);
}

// round 3
// speedup vs baseline: 2.4148x; 1.5989x over previous
#include <cuda_runtime.h>
#include <math.h>
#include <stdint.h>

// Problem capacities (fixed shapes per reference)
#define NMAXN 50000
#define EMAXE 200000
#define ETOTMAX (EMAXE + NMAXN)
#define GMAXG 1000

// ---------------- scratch (static device memory; no allocations allowed) ----
__device__ float g_bufA[(size_t)NMAXN * 1024];
__device__ float g_bufB[(size_t)NMAXN * 1024];
__device__ float g_bufC[(size_t)NMAXN * 1024];
__device__ float g_alS[NMAXN * 4];
__device__ float g_alD[NMAXN * 4];
__device__ int   g_degi[NMAXN];
__device__ int   g_rowptr[NMAXN + 1];
__device__ int   g_cursor[NMAXN];
__device__ int   g_csrsrc[ETOTMAX];
__device__ float g_dinv[NMAXN];
__device__ float g_bnsum[1024];
__device__ float g_bnsq[1024];
__device__ float g_bnscale[1024];
__device__ float g_bnshift[1024];
__device__ float g_cnt[GMAXG];
__device__ float g_z[GMAXG * 640];
__device__ float g_zf[GMAXG * 128];

// ---------------- CSR build -------------------------------------------------
__global__ void deg_build(const int* __restrict__ ei, int E, int Etot,
                          int* __restrict__ degi)
{
    int e = blockIdx.x * blockDim.x + threadIdx.x;
    if (e >= Etot) return;
    int d = (e < E) ? ei[E + e] : (e - E);
    atomicAdd(degi + d, 1);
}

// single-block scan over n entries (1024 threads)
__global__ void scan_kernel(const int* __restrict__ degi, int* __restrict__ rowptr,
                            int* __restrict__ cursor, int n)
{
    __shared__ int sm[32];
    __shared__ int s_carry;
    int tid = threadIdx.x;
    int lane = tid & 31, w = tid >> 5;
    if (tid == 0) s_carry = 0;
    __syncthreads();
    for (int base = 0; base < n; base += 1024) {
        int i = base + tid;
        int v = (i < n) ? degi[i] : 0;
        int x = v;
#pragma unroll
        for (int o = 1; o < 32; o <<= 1) {
            int y = __shfl_up_sync(0xFFFFFFFFu, x, o);
            if (lane >= o) x += y;
        }
        if (lane == 31) sm[w] = x;
        __syncthreads();
        if (w == 0) {
            int y = sm[lane];
#pragma unroll
            for (int o = 1; o < 32; o <<= 1) {
                int z = __shfl_up_sync(0xFFFFFFFFu, y, o);
                if (lane >= o) y += z;
            }
            sm[lane] = y;
        }
        __syncthreads();
        int incl = x + (w ? sm[w - 1] : 0);
        int excl = incl - v;
        int carry = s_carry;
        if (i < n) { rowptr[i] = carry + excl; cursor[i] = carry + excl; }
        __syncthreads();
        if (tid == 1023) s_carry = carry + incl;
        __syncthreads();
    }
    if (tid == 0) rowptr[n] = s_carry;
}

__global__ void csr_scatter(const int* __restrict__ ei, int E, int Etot,
                            int* __restrict__ cursor, int* __restrict__ csrsrc)
{
    int e = blockIdx.x * blockDim.x + threadIdx.x;
    if (e >= Etot) return;
    int s, d;
    if (e < E) { s = ei[e]; d = ei[E + e]; }
    else       { s = e - E; d = e - E; }
    int pos = atomicAdd(cursor + d, 1);
    csrsrc[pos] = s;
}

__global__ void dinv_kernel(const int* __restrict__ rowptr, float* __restrict__ dinv,
                            int n)
{
    int i = blockIdx.x * blockDim.x + threadIdx.x;
    if (i >= n) return;
    float deg = (float)(rowptr[i + 1] - rowptr[i]);
    dinv[i] = rsqrtf(fmaxf(deg, 1.0f));
}

// ---------------- TF32 tensor-core GEMM -------------------------------------
// C[M,Nc] = op(A)[M,K] @ B[K,Nc]; op = identity or relu(A*scale[k]+shift[k]).
__device__ __forceinline__ float to_tf32(float x) {
    uint32_t u;
    asm("cvt.rna.tf32.f32 %0, %1;" : "=r"(u) : "f"(x));
    return __uint_as_float(u);
}

__device__ __forceinline__ void mma_tf32(float c[4], const float a[4], const float b[2]) {
    asm volatile(
        "mma.sync.aligned.m16n8k8.row.col.f32.tf32.tf32.f32 "
        "{%0,%1,%2,%3}, {%4,%5,%6,%7}, {%8,%9}, {%0,%1,%2,%3};"
        : "+f"(c[0]), "+f"(c[1]), "+f"(c[2]), "+f"(c[3])
        : "r"(__float_as_uint(a[0])), "r"(__float_as_uint(a[1])),
          "r"(__float_as_uint(a[2])), "r"(__float_as_uint(a[3])),
          "r"(__float_as_uint(b[0])), "r"(__float_as_uint(b[1])));
}

template <bool BNRELU>
__global__ __launch_bounds__(256, 2) void tf32gemm(
    const float* __restrict__ A, const float* __restrict__ B,
    float* __restrict__ C, int M, int Nc, int K,
    const float* __restrict__ scale, const float* __restrict__ shift)
{
    __shared__ float As[128][36];
    __shared__ float Bs[32][136];

    int tid = threadIdx.x;
    int lane = tid & 31;
    int wid = tid >> 5;
    int warpM = (wid >> 2) * 64;
    int warpN = (wid & 3) * 32;
    int r = lane >> 2;
    int cq = lane & 3;

    int blockM = blockIdx.y * 128;
    int blockN = blockIdx.x * 128;

    int acol = (tid & 7) * 4;
    int arow0 = tid >> 3;
    int bcol = (tid & 31) * 4;
    int brow0 = tid >> 5;

    float acc[4][4][4];
#pragma unroll
    for (int mt = 0; mt < 4; mt++)
#pragma unroll
        for (int nt = 0; nt < 4; nt++)
#pragma unroll
            for (int i = 0; i < 4; i++) acc[mt][nt][i] = 0.0f;

    for (int k0 = 0; k0 < K; k0 += 32) {
        float4 sc4, sh4;
        if (BNRELU) {
            sc4 = *(const float4*)(scale + k0 + acol);
            sh4 = *(const float4*)(shift + k0 + acol);
        }
#pragma unroll
        for (int i = 0; i < 4; i++) {
            int row = blockM + arow0 + i * 32;
            float4 v = make_float4(0.f, 0.f, 0.f, 0.f);
            if (row < M) v = *(const float4*)(A + (size_t)row * K + k0 + acol);
            if (BNRELU) {
                v.x = fmaxf(fmaf(v.x, sc4.x, sh4.x), 0.f);
                v.y = fmaxf(fmaf(v.y, sc4.y, sh4.y), 0.f);
                v.z = fmaxf(fmaf(v.z, sc4.z, sh4.z), 0.f);
                v.w = fmaxf(fmaf(v.w, sc4.w, sh4.w), 0.f);
            }
            v.x = to_tf32(v.x); v.y = to_tf32(v.y);
            v.z = to_tf32(v.z); v.w = to_tf32(v.w);
            *(float4*)&As[arow0 + i * 32][acol] = v;
        }
#pragma unroll
        for (int i = 0; i < 4; i++) {
            int kr = brow0 + i * 8;
            float4 v = *(const float4*)(B + (size_t)(k0 + kr) * Nc + blockN + bcol);
            v.x = to_tf32(v.x); v.y = to_tf32(v.y);
            v.z = to_tf32(v.z); v.w = to_tf32(v.w);
            *(float4*)&Bs[kr][bcol] = v;
        }
        __syncthreads();

#pragma unroll
        for (int kk = 0; kk < 4; kk++) {
            int kb = kk * 8;
            float a[4][4], b[4][2];
#pragma unroll
            for (int mt = 0; mt < 4; mt++) {
                int m = warpM + mt * 16 + r;
                a[mt][0] = As[m][kb + cq];
                a[mt][1] = As[m + 8][kb + cq];
                a[mt][2] = As[m][kb + cq + 4];
                a[mt][3] = As[m + 8][kb + cq + 4];
            }
#pragma unroll
            for (int nt = 0; nt < 4; nt++) {
                int n = warpN + nt * 8 + r;
                b[nt][0] = Bs[kb + cq][n];
                b[nt][1] = Bs[kb + cq + 4][n];
            }
#pragma unroll
            for (int mt = 0; mt < 4; mt++)
#pragma unroll
                for (int nt = 0; nt < 4; nt++)
                    mma_tf32(acc[mt][nt], a[mt], b[nt]);
        }
        __syncthreads();
    }

#pragma unroll
    for (int mt = 0; mt < 4; mt++) {
        int row0 = blockM + warpM + mt * 16 + r;
#pragma unroll
        for (int nt = 0; nt < 4; nt++) {
            int col = blockN + warpN + nt * 8 + cq * 2;
            if (row0 < M)
                *(float2*)(C + (size_t)row0 * Nc + col) =
                    make_float2(acc[mt][nt][0], acc[mt][nt][1]);
            if (row0 + 8 < M)
                *(float2*)(C + (size_t)(row0 + 8) * Nc + col) =
                    make_float2(acc[mt][nt][2], acc[mt][nt][3]);
        }
    }
}

// ---------------- fp32 SGEMM (small head GEMMs) ------------------------------
template <bool RELU>
__global__ __launch_bounds__(256) void sgemm(
    const float* __restrict__ A, const float* __restrict__ B,
    const float* __restrict__ bias, float* __restrict__ C,
    int M, int Nc, int K, int lda, int ldc)
{
    __shared__ float As[8][128];
    __shared__ float Bs[8][128];

    int tid = threadIdx.x;
    int bx = blockIdx.x;
    int by = blockIdx.y;

    int tx = tid % 16;
    int ty = tid / 16;

    int rowA = by * 128 + tid / 2;
    int colA = (tid % 2) * 4;
    int rowB = tid / 32;
    int colB = (tid % 32) * 4;

    float acc[8][8];
#pragma unroll
    for (int i = 0; i < 8; i++)
#pragma unroll
        for (int j = 0; j < 8; j++) acc[i][j] = 0.0f;

    for (int k0 = 0; k0 < K; k0 += 8) {
        float4 av = make_float4(0.f, 0.f, 0.f, 0.f);
        if (rowA < M)
            av = *(const float4*)(A + (size_t)rowA * lda + k0 + colA);
        As[colA + 0][tid / 2] = av.x;
        As[colA + 1][tid / 2] = av.y;
        As[colA + 2][tid / 2] = av.z;
        As[colA + 3][tid / 2] = av.w;

        float4 bv = *(const float4*)(B + (size_t)(k0 + rowB) * Nc + bx * 128 + colB);
        *(float4*)(&Bs[rowB][colB]) = bv;

        __syncthreads();

#pragma unroll
        for (int kk = 0; kk < 8; kk++) {
            float ra[8], rb[8];
#pragma unroll
            for (int i = 0; i < 8; i++) ra[i] = As[kk][ty * 8 + i];
#pragma unroll
            for (int j = 0; j < 8; j++) rb[j] = Bs[kk][tx * 8 + j];
#pragma unroll
            for (int i = 0; i < 8; i++)
#pragma unroll
                for (int j = 0; j < 8; j++) acc[i][j] = fmaf(ra[i], rb[j], acc[i][j]);
        }
        __syncthreads();
    }

#pragma unroll
    for (int i = 0; i < 8; i++) {
        int row = by * 128 + ty * 8 + i;
        if (row >= M) continue;
#pragma unroll
        for (int j = 0; j < 8; j++) {
            int col = bx * 128 + tx * 8 + j;
            float v = acc[i][j];
            if (bias) v += bias[col];
            if (RELU) v = v > 0.f ? v : 0.f;
            C[(size_t)row * ldc + col] = v;
        }
    }
}

// ---------------- GAT attention ---------------------------------------------
__global__ void gat_alphas(const float* __restrict__ h, const float* __restrict__ aS,
                           const float* __restrict__ aD, float* __restrict__ alS,
                           float* __restrict__ alD, int n, int C)
{
    int warp = (blockIdx.x * blockDim.x + threadIdx.x) >> 5;
    int lane = threadIdx.x & 31;
    if (warp >= n * 4) return;
    int node = warp >> 2;
    int hh = warp & 3;
    const float* hp = h + (size_t)node * 4 * C + hh * C;
    const float* as = aS + hh * C;
    const float* ad = aD + hh * C;
    float s = 0.f, d = 0.f;
    for (int c = lane; c < C; c += 32) {
        float v = hp[c];
        s += v * as[c];
        d += v * ad[c];
    }
#pragma unroll
    for (int o = 16; o; o >>= 1) {
        s += __shfl_down_sync(0xFFFFFFFFu, s, o);
        d += __shfl_down_sync(0xFFFFFFFFu, d, o);
    }
    if (lane == 0) { alS[node * 4 + hh] = s; alD[node * 4 + hh] = d; }
}

// ---- fused per-destination GAT softmax + gather ----------------------------
// One block (NT=128 threads) per destination node. HC in {512, 1024}.
template <int HC>
__global__ __launch_bounds__(128) void gat_gather(
    const int* __restrict__ rowptr, const int* __restrict__ csrsrc,
    const float* __restrict__ alS, const float* __restrict__ alD,
    const float* __restrict__ h, float* __restrict__ out)
{
    constexpr int NT = 128;
    constexpr int VEC = HC / (4 * NT);    // float4s per thread
    constexpr int CPH = HC / 4;           // channels per head

    __shared__ float s_red[16];
    __shared__ float s_bm[4];
    __shared__ float s_binv[4];
    __shared__ float s_al[32][4];
    __shared__ int   s_src[32];

    int d = blockIdx.x;
    int tid = threadIdx.x;
    int lane = tid & 31, w = tid >> 5;
    int beg = rowptr[d], end = rowptr[d + 1];

    float4 ad4 = *(const float4*)(alD + (size_t)d * 4);
    float adv[4] = {ad4.x, ad4.y, ad4.z, ad4.w};

    // ---- phase A: per-head max over incoming edges
    float mx[4] = {-INFINITY, -INFINITY, -INFINITY, -INFINITY};
    for (int i = beg + tid; i < end; i += NT) {
        int s = csrsrc[i];
        float4 as4 = *(const float4*)(alS + (size_t)s * 4);
        float l[4] = {as4.x + adv[0], as4.y + adv[1], as4.z + adv[2], as4.w + adv[3]};
#pragma unroll
        for (int hh = 0; hh < 4; hh++) {
            float t = l[hh];
            t = t > 0.f ? t : 0.2f * t;
            mx[hh] = fmaxf(mx[hh], t);
        }
    }
#pragma unroll
    for (int hh = 0; hh < 4; hh++)
#pragma unroll
        for (int o = 16; o; o >>= 1)
            mx[hh] = fmaxf(mx[hh], __shfl_xor_sync(0xFFFFFFFFu, mx[hh], o));
    if (lane == 0) {
#pragma unroll
        for (int hh = 0; hh < 4; hh++) s_red[w * 4 + hh] = mx[hh];
    }
    __syncthreads();
    if (tid < 4) {
        float r = s_red[tid];
        r = fmaxf(r, s_red[4 + tid]);
        r = fmaxf(r, s_red[8 + tid]);
        r = fmaxf(r, s_red[12 + tid]);
        s_bm[tid] = r;
    }
    __syncthreads();
    float bm[4] = {s_bm[0], s_bm[1], s_bm[2], s_bm[3]};

    // ---- phase B: per-head sum of exp
    float sme[4] = {0.f, 0.f, 0.f, 0.f};
    for (int i = beg + tid; i < end; i += NT) {
        int s = csrsrc[i];
        float4 as4 = *(const float4*)(alS + (size_t)s * 4);
        float l[4] = {as4.x + adv[0], as4.y + adv[1], as4.z + adv[2], as4.w + adv[3]};
#pragma unroll
        for (int hh = 0; hh < 4; hh++) {
            float t = l[hh];
            t = t > 0.f ? t : 0.2f * t;
            sme[hh] += expf(t - bm[hh]);
        }
    }
#pragma unroll
    for (int hh = 0; hh < 4; hh++)
#pragma unroll
        for (int o = 16; o; o >>= 1)
            sme[hh] += __shfl_xor_sync(0xFFFFFFFFu, sme[hh], o);
    if (lane == 0) {
#pragma unroll
        for (int hh = 0; hh < 4; hh++) s_red[w * 4 + hh] = sme[hh];
    }
    __syncthreads();
    if (tid < 4) {
        float r = s_red[tid] + s_red[4 + tid] + s_red[8 + tid] + s_red[12 + tid];
        s_binv[tid] = 1.0f / fmaxf(r, 1e-16f);
    }
    __syncthreads();

    // ---- phase C: weighted gather, chunked 32 edges at a time
    float4 acc[VEC];
#pragma unroll
    for (int v = 0; v < VEC; v++) acc[v] = make_float4(0.f, 0.f, 0.f, 0.f);

    int headOf[VEC];
#pragma unroll
    for (int v = 0; v < VEC; v++) headOf[v] = (tid * 4 + v * NT * 4) / CPH;

    for (int c0 = beg; c0 < end; c0 += 32) {
        int cnt = min(32, end - c0);
        if (tid < cnt * 4) {
            int j = tid >> 2, hh = tid & 3;
            int s = csrsrc[c0 + j];
            if (hh == 0) s_src[j] = s;
            float t = alS[(size_t)s * 4 + hh] + adv[hh];
            t = t > 0.f ? t : 0.2f * t;
            s_al[j][hh] = expf(t - s_bm[hh]) * s_binv[hh];
        }
        __syncthreads();
        for (int j = 0; j < cnt; j++) {
            int s = s_src[j];
            const float4* hp = (const float4*)(h + (size_t)s * HC);
#pragma unroll
            for (int v = 0; v < VEC; v++) {
                float a = s_al[j][headOf[v]];
                float4 hv = hp[tid + v * NT];
                acc[v].x = fmaf(a, hv.x, acc[v].x);
                acc[v].y = fmaf(a, hv.y, acc[v].y);
                acc[v].z = fmaf(a, hv.z, acc[v].z);
                acc[v].w = fmaf(a, hv.w, acc[v].w);
            }
        }
        __syncthreads();
    }

    float4* op = (float4*)(out + (size_t)d * HC);
#pragma unroll
    for (int v = 0; v < VEC; v++) op[tid + v * NT] = acc[v];
}

// ---------------- GCN gather -------------------------------------------------
// One block of 64 threads per destination node, HC = 256.
__global__ __launch_bounds__(64) void gcn_gather(
    const int* __restrict__ rowptr, const int* __restrict__ csrsrc,
    const float* __restrict__ dinv, const float* __restrict__ h,
    float* __restrict__ out)
{
    int d = blockIdx.x;
    int tid = threadIdx.x;
    int beg = rowptr[d], end = rowptr[d + 1];
    float dd = dinv[d];

    float4 acc = make_float4(0.f, 0.f, 0.f, 0.f);
    for (int i = beg; i < end; i++) {
        int s = csrsrc[i];
        float nrm = dinv[s] * dd;
        float4 v = *(const float4*)(h + (size_t)s * 256 + tid * 4);
        acc.x = fmaf(nrm, v.x, acc.x);
        acc.y = fmaf(nrm, v.y, acc.y);
        acc.z = fmaf(nrm, v.z, acc.z);
        acc.w = fmaf(nrm, v.w, acc.w);
    }
    *(float4*)(out + (size_t)d * 256 + tid * 4) = acc;
}

// ---------------- BatchNorm -------------------------------------------------
__global__ void bn_stats(const float* __restrict__ x, int rows, int K,
                         float* __restrict__ sum, float* __restrict__ sq)
{
    int col = blockIdx.x * blockDim.x + threadIdx.x;
    float s = 0.f, q = 0.f;
    for (int r = blockIdx.y; r < rows; r += gridDim.y) {
        float v = x[(size_t)r * K + col];
        s += v;
        q += v * v;
    }
    atomicAdd(sum + col, s);
    atomicAdd(sq + col, q);
}

__global__ void bn_finalize(const float* __restrict__ sum, const float* __restrict__ sq,
                            const float* __restrict__ g, const float* __restrict__ b,
                            int rows, int K, float* __restrict__ scale,
                            float* __restrict__ shift)
{
    int c = blockIdx.x * blockDim.x + threadIdx.x;
    if (c >= K) return;
    float inv_n = 1.0f / (float)rows;
    float mu = sum[c] * inv_n;
    float var = sq[c] * inv_n - mu * mu;
    float sc = g[c] * rsqrtf(var + 1e-5f);
    scale[c] = sc;
    shift[c] = b[c] - mu * sc;
}

__global__ void bn_apply_relu(float* __restrict__ x, const float* __restrict__ scale,
                              const float* __restrict__ shift, size_t total, int K)
{
    for (size_t i = (size_t)blockIdx.x * blockDim.x + threadIdx.x; i < total;
         i += (size_t)gridDim.x * blockDim.x) {
        int c = (int)(i % K);
        float v = x[i] * scale[c] + shift[c];
        x[i] = v > 0.f ? v : 0.f;
    }
}

// ---------------- Pooling (applies BN+relu of GCN output on the fly) ---------
__global__ void pool_cnt(const int* __restrict__ batch, int n, float* __restrict__ cnt)
{
    int i = blockIdx.x * blockDim.x + threadIdx.x;
    if (i >= n) return;
    atomicAdd(cnt + batch[i], 1.0f);
}

__global__ void pool_kernel(const float* __restrict__ h, const int* __restrict__ batch,
                            const float* __restrict__ scale,
                            const float* __restrict__ shift,
                            int n, float* __restrict__ z)
{
    size_t total = (size_t)n * 256;
    for (size_t i = (size_t)blockIdx.x * blockDim.x + threadIdx.x; i < total;
         i += (size_t)gridDim.x * blockDim.x) {
        int node = (int)(i >> 8);
        int c = (int)(i & 255);
        int g = batch[node];
        float v = fmaxf(fmaf(h[i], scale[c], shift[c]), 0.f);
        atomicAdd(z + (size_t)g * 640 + c, v);
        atomicMax((int*)(z + (size_t)g * 640 + 256 + c), __float_as_int(v));
    }
}

__global__ void pool_div(float* __restrict__ z, const float* __restrict__ cnt, int G)
{
    int i = blockIdx.x * blockDim.x + threadIdx.x;
    if (i >= G * 256) return;
    int g = i >> 8;
    int c = i & 255;
    z[(size_t)g * 640 + c] /= fmaxf(cnt[g], 1.0f);
}

// ---------------- Head ------------------------------------------------------
__global__ void head_final(const float* __restrict__ zf, const float* __restrict__ Wf2,
                           const float* __restrict__ bf2, float* __restrict__ out)
{
    int g = blockIdx.x;
    int t = threadIdx.x;
    float v = zf[(size_t)g * 128 + t] * Wf2[t];
#pragma unroll
    for (int o = 16; o; o >>= 1) v += __shfl_down_sync(0xFFFFFFFFu, v, o);
    __shared__ float sm[4];
    if ((t & 31) == 0) sm[t >> 5] = v;
    __syncthreads();
    if (t == 0) {
        float s = sm[0] + sm[1] + sm[2] + sm[3] + bf2[0];
        out[g] = 1.0f / (1.0f + expf(-s));
    }
}

// ---------------- launch ----------------------------------------------------
extern "C" void kernel_launch(void* const* d_in, const int* in_sizes, int n_in,
                              void* d_out, int out_size)
{
    const float* x    = (const float*)d_in[0];
    const int*   ei   = (const int*)d_in[1];
    const int*   batch= (const int*)d_in[2];
    const float* fp   = (const float*)d_in[3];
    const float* W1   = (const float*)d_in[4];
    const float* a1s  = (const float*)d_in[5];
    const float* a1d  = (const float*)d_in[6];
    const float* bn1g = (const float*)d_in[8];
    const float* bn1b = (const float*)d_in[9];
    const float* W2   = (const float*)d_in[10];
    const float* a2s  = (const float*)d_in[11];
    const float* a2d  = (const float*)d_in[12];
    const float* bn2g = (const float*)d_in[14];
    const float* bn2b = (const float*)d_in[15];
    const float* Wg   = (const float*)d_in[16];
    const float* bn3g = (const float*)d_in[18];
    const float* bn3b = (const float*)d_in[19];
    const float* Ws   = (const float*)d_in[20];
    const float* bs   = (const float*)d_in[21];
    const float* Wf1  = (const float*)d_in[22];
    const float* bnfg = (const float*)d_in[24];
    const float* bnfb = (const float*)d_in[25];
    const float* Wf2  = (const float*)d_in[26];
    const float* bf2  = (const float*)d_in[27];
    float* out = (float*)d_out;

    int n    = in_sizes[0] / 64;
    int E    = in_sizes[1] / 2;
    int Etot = E + n;
    int G    = in_sizes[3] / 128;

    float *bufA, *bufB, *bufC, *alS, *alD, *dinv;
    float *bnsum, *bnsq, *bnscale, *bnshift, *cnt, *z, *zf;
    int *degi, *rowptr, *cursor, *csrsrc;
    cudaGetSymbolAddress((void**)&bufA, g_bufA);
    cudaGetSymbolAddress((void**)&bufB, g_bufB);
    cudaGetSymbolAddress((void**)&bufC, g_bufC);
    cudaGetSymbolAddress((void**)&alS, g_alS);
    cudaGetSymbolAddress((void**)&alD, g_alD);
    cudaGetSymbolAddress((void**)&degi, g_degi);
    cudaGetSymbolAddress((void**)&rowptr, g_rowptr);
    cudaGetSymbolAddress((void**)&cursor, g_cursor);
    cudaGetSymbolAddress((void**)&csrsrc, g_csrsrc);
    cudaGetSymbolAddress((void**)&dinv, g_dinv);
    cudaGetSymbolAddress((void**)&bnsum, g_bnsum);
    cudaGetSymbolAddress((void**)&bnsq, g_bnsq);
    cudaGetSymbolAddress((void**)&bnscale, g_bnscale);
    cudaGetSymbolAddress((void**)&bnshift, g_bnshift);
    cudaGetSymbolAddress((void**)&cnt, g_cnt);
    cudaGetSymbolAddress((void**)&z, g_z);
    cudaGetSymbolAddress((void**)&zf, g_zf);

    auto gemm_tc = [&](const float* A, const float* B, float* C,
                       int M, int Nc, int K, const float* sc, const float* sh) {
        dim3 grid(Nc / 128, (M + 127) / 128);
        if (sc) tf32gemm<true><<<grid, 256>>>(A, B, C, M, Nc, K, sc, sh);
        else    tf32gemm<false><<<grid, 256>>>(A, B, C, M, Nc, K, nullptr, nullptr);
    };

    auto gemm = [&](const float* A, const float* B, const float* bias, float* C,
                    int M, int Nc, int K, int lda, int ldc, bool relu) {
        dim3 grid(Nc / 128, (M + 127) / 128);
        if (relu) sgemm<true><<<grid, 256>>>(A, B, bias, C, M, Nc, K, lda, ldc);
        else      sgemm<false><<<grid, 256>>>(A, B, bias, C, M, Nc, K, lda, ldc);
    };

    auto bnstats = [&](const float* Xp, int rows, int K, const float* gg,
                       const float* bb) {
        cudaMemsetAsync(bnsum, 0, K * sizeof(float));
        cudaMemsetAsync(bnsq, 0, K * sizeof(float));
        dim3 g1(K / 128, 128);
        bn_stats<<<g1, 128>>>(Xp, rows, K, bnsum, bnsq);
        bn_finalize<<<(K + 127) / 128, 128>>>(bnsum, bnsq, gg, bb, rows, K,
                                              bnscale, bnshift);
    };

    // ---- CSR build (dst-sorted), reused by GAT1/GAT2/GCN
    cudaMemsetAsync(degi, 0, n * sizeof(int));
    deg_build<<<(Etot + 255) / 256, 256>>>(ei, E, Etot, degi);
    scan_kernel<<<1, 1024>>>(degi, rowptr, cursor, n);
    csr_scatter<<<(Etot + 255) / 256, 256>>>(ei, E, Etot, cursor, csrsrc);
    dinv_kernel<<<(n + 255) / 256, 256>>>(rowptr, dinv, n);

    // ---- GAT layer 1: bufA = x@W1; gather -> bufB; BN stats (apply deferred)
    gemm_tc(x, W1, bufA, n, 512, 64, nullptr, nullptr);
    gat_alphas<<<(n * 4 + 7) / 8, 256>>>(bufA, a1s, a1d, alS, alD, n, 128);
    gat_gather<512><<<n, 128>>>(rowptr, csrsrc, alS, alD, bufA, bufB);
    bnstats(bufB, n, 512, bn1g, bn1b);

    // ---- GAT layer 2: bufC = relu(bn(bufB))@W2; gather -> bufA; BN stats
    gemm_tc(bufB, W2, bufC, n, 1024, 512, bnscale, bnshift);
    gat_alphas<<<(n * 4 + 7) / 8, 256>>>(bufC, a2s, a2d, alS, alD, n, 256);
    gat_gather<1024><<<n, 128>>>(rowptr, csrsrc, alS, alD, bufC, bufA);
    bnstats(bufA, n, 1024, bn2g, bn2b);

    // ---- GCN: bufB = relu(bn(bufA))@Wg [N,256]; gather -> bufC; BN stats
    gemm_tc(bufA, Wg, bufB, n, 256, 1024, bnscale, bnshift);
    gcn_gather<<<n, 64>>>(rowptr, csrsrc, dinv, bufB, bufC);
    bnstats(bufC, n, 256, bn3g, bn3b);

    // ---- Pooling into z[G,640] (BN+relu of bufC applied on the fly)
    cudaMemsetAsync(cnt, 0, G * sizeof(float));
    cudaMemsetAsync(z, 0, (size_t)G * 640 * sizeof(float));
    pool_cnt<<<(n + 255) / 256, 256>>>(batch, n, cnt);
    pool_kernel<<<8192, 256>>>(bufC, batch, bnscale, bnshift, n, z);
    pool_div<<<(G * 256 + 255) / 256, 256>>>(z, cnt, G);

    // ---- solvent MLP: relu(fp @ Ws + bs) -> z[:,512:640]
    gemm(fp, Ws, bs, z + 512, G, 128, 128, 128, 640, true);

    // ---- head: zf = z @ Wf1 (bf1 cancels under BN); BN; relu; sigmoid
    gemm(z, Wf1, nullptr, zf, G, 128, 640, 640, 128, false);
    {
        cudaMemsetAsync(bnsum, 0, 128 * sizeof(float));
        cudaMemsetAsync(bnsq, 0, 128 * sizeof(float));
        dim3 g1(1, 128);
        bn_stats<<<g1, 128>>>(zf, G, 128, bnsum, bnsq);
        bn_finalize<<<1, 128>>>(bnsum, bnsq, bnfg, bnfb, G, 128, bnscale, bnshift);
        bn_apply_relu<<<((size_t)G * 128 + 255) / 256, 256>>>(zf, bnscale, bnshift,
                                                              (size_t)G * 128, 128);
    }
    head_final<<<G, 128>>>(zf, Wf2, bf2, out);
}